// round 6
// baseline (speedup 1.0000x reference)
#include <cuda_runtime.h>
#include <math.h>

// ---------------------------------------------------------------------------
// DictionaryMatchingTv — GB300 sm_103a
//   inputs (metadata order):
//     0: slice_signal  [N*16]  float32   (N = 36864)
//     1: db_mag        [D*16]  float32   (D = 4000)
//     2: db_t2s_s      [D]     float32
//     3: db_b1s        [D]     float32
//     4: delta_t_r2p_ms[16]    float32
//   output: [t2 (N) | b1 (N) | min_dist (N)] float32
// ---------------------------------------------------------------------------

#define ETL   16
#define MAXD  8192   // max dictionary atoms supported

__device__ float g_main[(MAXD / 2) * 16];  // pair-interleaved compacted atoms
__device__ float g_bias[(MAXD / 2) * 2];   // per-atom bias = -0.5*d2 (pair-packed)
__device__ float g_full[MAXD * ETL];       // full normalized atoms (fallback)
__device__ float g_d2[MAXD];               // ||atom||^2 (fallback)

// ---- f32x2 packed helpers (Blackwell-only PTX) -----------------------------
__device__ __forceinline__ unsigned long long pkf(float lo, float hi) {
    unsigned long long r;
    asm("mov.b64 %0, {%1, %2};" : "=l"(r) : "f"(lo), "f"(hi));
    return r;
}
__device__ __forceinline__ void unpk(float& lo, float& hi, unsigned long long v) {
    asm("mov.b64 {%0, %1}, %2;" : "=f"(lo), "=f"(hi) : "l"(v));
}
__device__ __forceinline__ void fma2(unsigned long long& d, unsigned long long a,
                                     unsigned long long b) {
    asm("fma.rn.f32x2 %0, %1, %2, %0;" : "+l"(d) : "l"(a), "l"(b));
}

// ---------------------------------------------------------------------------
// Kernel 1: normalize dictionary atoms; build pair-interleaved compact table.
//   g_main[pr*16 + j*2 + slot] = compacted value j (0..7) of atom (2*pr+slot)
//   g_bias[pr*2 + slot]        = -0.5*d2   (pad atoms: -1e30, never win)
// Mask/compaction computed locally per thread (no separate kernel).
// ---------------------------------------------------------------------------
__global__ void k_atoms(const float* __restrict__ db_mag,
                        const float* __restrict__ delta, int D, int Dpad) {
    int a = blockIdx.x * blockDim.x + threadIdx.x;
    if (a >= Dpad) return;

    int cols[ETL];
    int M = 0;
#pragma unroll
    for (int e = 0; e < ETL; e++) {
        if (delta[e] * 1e-3f < 1e-3f) cols[M++] = e;
    }

    int pr = a >> 1, slot = a & 1;
    float c[8];
#pragma unroll
    for (int j = 0; j < 8; j++) c[j] = 0.0f;
    float bias = -1e30f;  // padding sentinel

    if (a < D) {
        float w[ETL];
        float nn = 0.0f;
#pragma unroll
        for (int i = 0; i < ETL; i++) {
            float m = (delta[i] * 1e-3f < 1e-3f) ? 1.0f : 0.0f;
            float v = db_mag[a * ETL + i] * m;
            w[i] = v;
            nn += v * v;
        }
        nn = sqrtf(nn);
        float inv = (nn > 0.0f) ? 1.0f / nn : 0.0f;  // nan_to_num semantics
        float db[ETL];
        float d2 = 0.0f;
#pragma unroll
        for (int i = 0; i < ETL; i++) {
            db[i] = w[i] * inv;
            d2 += db[i] * db[i];
            g_full[a * ETL + i] = db[i];
        }
        g_d2[a] = d2;
        bias = -0.5f * d2;
        int mm = (M < 8) ? M : 8;
        for (int j = 0; j < mm; j++) c[j] = db[cols[j]];
    }

    float* rec = &g_main[pr * 16];
#pragma unroll
    for (int j = 0; j < 8; j++) rec[j * 2 + slot] = c[j];
    g_bias[pr * 2 + slot] = bias;
}

// ---------------------------------------------------------------------------
// Kernel 2: per-pixel dictionary match. 512 threads/block, 2 threads/pixel.
// Thread parity (tid&1) selects dictionary half; merge via shfl.xor(1).
// score = dot - 0.5*d2 (bias preloaded into accumulator); dist^2 = s2 - 2*score
// ---------------------------------------------------------------------------
__global__ void __launch_bounds__(512, 1)
k_match(const float* __restrict__ sig, const float* __restrict__ t2s,
        const float* __restrict__ b1s, const float* __restrict__ delta,
        float* __restrict__ out, int N, int D) {
    extern __shared__ float sm[];
    const int Dpad = (D + 1) & ~1;
    const int NP = Dpad >> 1;
    float* smb = sm + NP * 16;  // bias region

    // ---- stage atom tables to shared ----
    {
        const uint4* src = (const uint4*)g_main;
        uint4* dst = (uint4*)sm;
        const int n4 = NP * 4;
        for (int i = threadIdx.x; i < n4; i += blockDim.x) dst[i] = src[i];
        const int nb = NP * 2;
        for (int i = threadIdx.x; i < nb; i += blockDim.x) smb[i] = g_bias[i];
    }

    // ---- local mask/compaction table ----
    int cols[ETL];
    int M = 0;
#pragma unroll
    for (int e = 0; e < ETL; e++) {
        if (delta[e] * 1e-3f < 1e-3f) cols[M++] = e;
    }
    __syncthreads();

    const int tid = threadIdx.x;
    const int pix = blockIdx.x * (blockDim.x >> 1) + (tid >> 1);
    const int half = tid & 1;
    const bool valid = (pix < N);
    const int n = valid ? pix : (N - 1);

    // ---- per-pixel signal normalize (two-step, matching reference) ----
    const float4* sp = (const float4*)(sig + (size_t)n * ETL);
    float4 f0 = sp[0], f1 = sp[1], f2 = sp[2], f3 = sp[3];
    float v[ETL] = {f0.x, f0.y, f0.z, f0.w, f1.x, f1.y, f1.z, f1.w,
                    f2.x, f2.y, f2.z, f2.w, f3.x, f3.y, f3.z, f3.w};
    float n1 = 0.0f;
#pragma unroll
    for (int i = 0; i < ETL; i++) n1 += v[i] * v[i];
    n1 = sqrtf(n1);
    float inv1 = (n1 > 0.0f) ? 1.0f / n1 : 0.0f;

    float best = -INFINITY;
    int atom = 0;
    float s2 = 0.0f;

    if (M <= 8) {
        // ---- fast path ----
        float w[8];
        int mm = (M < 8) ? M : 8;
        float n2 = 0.0f;
#pragma unroll
        for (int j = 0; j < 8; j++) {
            float x = (j < mm) ? v[cols[j]] * inv1 : 0.0f;
            w[j] = x;
            n2 += x * x;
        }
        n2 = sqrtf(n2);
        float inv2 = (n2 > 0.0f) ? 1.0f / n2 : 0.0f;
        unsigned long long spk[8];
#pragma unroll
        for (int j = 0; j < 8; j++) {
            float s = w[j] * inv2;
            s2 += s * s;
            spk[j] = pkf(s, s);
        }

        const int NPh = (NP + 1) >> 1;
        const int start = half ? NPh : 0;
        const int end = half ? NP : NPh;

        const unsigned long long* bptr = (const unsigned long long*)smb;
        float best0 = -INFINITY, best1 = -INFINITY;
        int bi0 = start, bi1 = start;

#pragma unroll 4
        for (int p = start; p < end; p++) {
            const float4* rec = (const float4*)sm + (p << 2);
            float4 qa = rec[0], qb = rec[1], qc = rec[2], qd = rec[3];
            unsigned long long acc = bptr[p];  // packed (-0.5*d2) pair
            fma2(acc, pkf(qa.x, qa.y), spk[0]);
            fma2(acc, pkf(qa.z, qa.w), spk[1]);
            fma2(acc, pkf(qb.x, qb.y), spk[2]);
            fma2(acc, pkf(qb.z, qb.w), spk[3]);
            fma2(acc, pkf(qc.x, qc.y), spk[4]);
            fma2(acc, pkf(qc.z, qc.w), spk[5]);
            fma2(acc, pkf(qd.x, qd.y), spk[6]);
            fma2(acc, pkf(qd.z, qd.w), spk[7]);
            float se, so;
            unpk(se, so, acc);
            if (se > best0) { best0 = se; bi0 = p; }
            if (so > best1) { best1 = so; bi1 = p; }
        }
        // even slot wins ties (lower atom index first, like jnp.argmin)
        if (best1 > best0) { best = best1; atom = 2 * bi1 + 1; }
        else               { best = best0; atom = 2 * bi0; }
    } else {
        // ---- generic fallback: any mask width; only half 0 works ----
        if (half == 0) {
            float u[ETL];
            float n2 = 0.0f;
#pragma unroll
            for (int i = 0; i < ETL; i++) {
                float m = (delta[i] * 1e-3f < 1e-3f) ? 1.0f : 0.0f;
                u[i] = v[i] * inv1 * m;
                n2 += u[i] * u[i];
            }
            n2 = sqrtf(n2);
            float inv2 = (n2 > 0.0f) ? 1.0f / n2 : 0.0f;
            float s[ETL];
#pragma unroll
            for (int i = 0; i < ETL; i++) { s[i] = u[i] * inv2; s2 += s[i] * s[i]; }
            best = -INFINITY;
            atom = 0;
            for (int d = 0; d < D; d++) {
                float dot = 0.0f;
#pragma unroll
                for (int i = 0; i < ETL; i++) dot += g_full[d * ETL + i] * s[i];
                float sc = dot - 0.5f * g_d2[d];
                if (sc > best) { best = sc; atom = d; }
            }
        }
    }

    // ---- merge halves (partner = adjacent lane) ----
    float ob = __shfl_xor_sync(0xffffffffu, best, 1);
    int oa = __shfl_xor_sync(0xffffffffu, atom, 1);

    if (half == 0 && valid) {
        // half0 atoms have strictly lower indices -> prefer on tie (strict >)
        if (ob > best) { best = ob; atom = oa; }
        if (atom >= D) atom = 0;  // padding safety (cannot actually win)
        float dist2 = s2 - 2.0f * best;
        float md = sqrtf(fmaxf(dist2, 0.0f));
        out[pix]         = t2s[atom];
        out[N + pix]     = b1s[atom];
        out[2 * N + pix] = md;
    }
}

// ---------------------------------------------------------------------------
extern "C" void kernel_launch(void* const* d_in, const int* in_sizes, int n_in,
                              void* d_out, int out_size) {
    const float* sig   = (const float*)d_in[0];
    const float* dbmag = (const float*)d_in[1];
    const float* t2s   = (const float*)d_in[2];
    const float* b1s   = (const float*)d_in[3];
    const float* delta = (const float*)d_in[4];

    const int D = in_sizes[2];                 // 4000
    const int N = in_sizes[0] / ETL;           // 36864
    const int Dpad = (D + 1) & ~1;
    const int NP = Dpad >> 1;
    const size_t smem = (size_t)NP * 18 * sizeof(float);  // 144 KB

    cudaFuncSetAttribute(k_match, cudaFuncAttributeMaxDynamicSharedMemorySize,
                         (int)smem);

    k_atoms<<<(Dpad + 127) / 128, 128>>>(dbmag, delta, D, Dpad);
    const int pixPerBlk = 256;
    int blocks = (N + pixPerBlk - 1) / pixPerBlk;
    k_match<<<blocks, 512, smem>>>(sig, t2s, b1s, delta, (float*)d_out, N, D);
}

// round 7
// speedup vs baseline: 1.2025x; 1.2025x over previous
#include <cuda_runtime.h>
#include <math.h>
#include <limits.h>

// ---------------------------------------------------------------------------
// DictionaryMatchingTv — GB300 sm_103a
//   inputs (metadata order):
//     0: slice_signal  [N*16]  float32   (N = 36864)
//     1: db_mag        [D*16]  float32   (D = 4000)
//     2: db_t2s_s      [D]     float32
//     3: db_b1s        [D]     float32
//     4: delta_t_r2p_ms[16]    float32
//   output: [t2 (N) | b1 (N) | min_dist (N)] float32
//
// Structure: atom PAIRS packed into f32x2 lanes (even atom in lane0, odd in
// lane1). Each thread matches 2 pixels against a 4-way interleaved slice of
// the pair list (pairs p ≡ s mod 4). Best tracked index-free via fmaxf with
// per-chunk snapshots; argmax index recovered by exact-equality rescan of the
// single winning chunk (identical asm fma chain -> bitwise reproducible).
// ---------------------------------------------------------------------------

#define ETL     16
#define MAXD    8192
#define NCHUNK  8
// max pairs after padding: ceil(ceil(ceil(MAXD/2)/4)/8)*8*4 = 4096
#define MAXNP2  4096

__device__ float g_recs[MAXNP2 * 20];   // 80-B records: 16 vals + 2 bias + pad
__device__ float g_full[MAXD * ETL];    // normalized atoms (generic fallback)
__device__ float g_d2[MAXD];            // ||atom||^2     (generic fallback)

// ---- f32x2 packed helpers (Blackwell-only PTX) -----------------------------
__device__ __forceinline__ unsigned long long pkf(float lo, float hi) {
    unsigned long long r;
    asm("mov.b64 %0, {%1, %2};" : "=l"(r) : "f"(lo), "f"(hi));
    return r;
}
__device__ __forceinline__ unsigned long long pku(unsigned lo, unsigned hi) {
    unsigned long long r;
    asm("mov.b64 %0, {%1, %2};" : "=l"(r) : "r"(lo), "r"(hi));
    return r;
}
__device__ __forceinline__ void unpk(float& lo, float& hi, unsigned long long v) {
    asm("mov.b64 {%0, %1}, %2;" : "=f"(lo), "=f"(hi) : "l"(v));
}
__device__ __forceinline__ void fma2(unsigned long long& d, unsigned long long a,
                                     unsigned long long b) {
    asm("fma.rn.f32x2 %0, %1, %2, %0;" : "+l"(d) : "l"(a), "l"(b));
}

// Shared scoring routine: MUST be the single definition used by both the main
// loop and the recovery rescan so results are bitwise identical.
__device__ __forceinline__ unsigned long long score_pair(
    const float* __restrict__ rec, const unsigned long long* __restrict__ spk) {
    uint4 qa = *(const uint4*)(rec);
    uint4 qb = *(const uint4*)(rec + 4);
    uint4 qc = *(const uint4*)(rec + 8);
    uint4 qd = *(const uint4*)(rec + 12);
    unsigned long long acc = *(const unsigned long long*)(rec + 16);  // bias
    fma2(acc, pku(qa.x, qa.y), spk[0]);
    fma2(acc, pku(qa.z, qa.w), spk[1]);
    fma2(acc, pku(qb.x, qb.y), spk[2]);
    fma2(acc, pku(qb.z, qb.w), spk[3]);
    fma2(acc, pku(qc.x, qc.y), spk[4]);
    fma2(acc, pku(qc.z, qc.w), spk[5]);
    fma2(acc, pku(qd.x, qd.y), spk[6]);
    fma2(acc, pku(qd.z, qd.w), spk[7]);
    return acc;
}

// ---------------------------------------------------------------------------
// Kernel 1: normalize atoms, build 80-B pair records (+ sentinels for padding)
//   rec[j*2 + slot] (j=0..7) = compacted SE value j of atom 2*pr+slot
//   rec[16 + slot]           = -0.5*d2   (pad atoms: -1e30, never win)
// ---------------------------------------------------------------------------
__global__ void k_atoms(const float* __restrict__ db_mag,
                        const float* __restrict__ delta, int D, int NP2) {
    int a = blockIdx.x * blockDim.x + threadIdx.x;
    if (a >= NP2 * 2) return;

    int cols[ETL];
    int M = 0;
#pragma unroll
    for (int e = 0; e < ETL; e++) {
        if (delta[e] * 1e-3f < 1e-3f) cols[M++] = e;
    }

    int pr = a >> 1, slot = a & 1;
    float c[8];
#pragma unroll
    for (int j = 0; j < 8; j++) c[j] = 0.0f;
    float bias = -1e30f;  // sentinel: score can never exceed real scores

    if (a < D) {
        float w[ETL];
        float nn = 0.0f;
#pragma unroll
        for (int i = 0; i < ETL; i++) {
            float m = (delta[i] * 1e-3f < 1e-3f) ? 1.0f : 0.0f;
            float v = db_mag[a * ETL + i] * m;
            w[i] = v;
            nn += v * v;
        }
        nn = sqrtf(nn);
        float inv = (nn > 0.0f) ? 1.0f / nn : 0.0f;  // nan_to_num semantics
        float db[ETL];
        float d2 = 0.0f;
#pragma unroll
        for (int i = 0; i < ETL; i++) {
            db[i] = w[i] * inv;
            d2 += db[i] * db[i];
            g_full[a * ETL + i] = db[i];
        }
        g_d2[a] = d2;
        bias = -0.5f * d2;
        int mm = (M < 8) ? M : 8;
        for (int j = 0; j < mm; j++) c[j] = db[cols[j]];
    }

    float* rec = &g_recs[pr * 20];
#pragma unroll
    for (int j = 0; j < 8; j++) rec[j * 2 + slot] = c[j];
    rec[16 + slot] = bias;
    if (slot == 0) { rec[18] = 0.0f; rec[19] = 0.0f; }
}

// ---------------------------------------------------------------------------
// Kernel 2: match. 512 thr/block, 256 pixels/block, 2 pixels/thread,
// 4-way interleaved dictionary split merged via shfl.
// ---------------------------------------------------------------------------
__global__ void __launch_bounds__(512, 1)
k_match(const float* __restrict__ sig, const float* __restrict__ t2s,
        const float* __restrict__ b1s, const float* __restrict__ delta,
        float* __restrict__ out, int N, int D, int NP2, int CH) {
    extern __shared__ float sm[];

    // ---- stage records to shared (uint4 copies, broadcast-read later) ----
    {
        const uint4* src = (const uint4*)g_recs;
        uint4* dst = (uint4*)sm;
        const int n4 = NP2 * 5;
        for (int i = threadIdx.x; i < n4; i += blockDim.x) dst[i] = src[i];
    }

    int cols[ETL];
    int M = 0;
#pragma unroll
    for (int e = 0; e < ETL; e++) {
        if (delta[e] * 1e-3f < 1e-3f) cols[M++] = e;
    }
    __syncthreads();

    const int tid = threadIdx.x;
    const int s = tid & 3;            // dictionary split 0..3
    const int g = tid >> 2;           // pixel group 0..127
    const int pix0 = blockIdx.x * 256 + g * 2;
    const int pix1 = pix0 + 1;
    const bool v0 = (pix0 < N), v1 = (pix1 < N);
    const int n0 = v0 ? pix0 : (N - 1);
    const int n1 = v1 ? pix1 : (N - 1);

    // ---- per-pixel normalize (two-step, matching reference) ----
    float s2A = 0.0f, s2B = 0.0f;
    unsigned long long spkA[8], spkB[8];
    float vA[ETL], vB[ETL];
    float inv1A, inv1B;
    {
        const float4* pa = (const float4*)(sig + (size_t)n0 * ETL);
        const float4* pb = (const float4*)(sig + (size_t)n1 * ETL);
        float4 a0 = pa[0], a1 = pa[1], a2 = pa[2], a3 = pa[3];
        float4 b0 = pb[0], b1 = pb[1], b2 = pb[2], b3 = pb[3];
        float ta[ETL] = {a0.x, a0.y, a0.z, a0.w, a1.x, a1.y, a1.z, a1.w,
                         a2.x, a2.y, a2.z, a2.w, a3.x, a3.y, a3.z, a3.w};
        float tb[ETL] = {b0.x, b0.y, b0.z, b0.w, b1.x, b1.y, b1.z, b1.w,
                         b2.x, b2.y, b2.z, b2.w, b3.x, b3.y, b3.z, b3.w};
        float na = 0.0f, nb = 0.0f;
#pragma unroll
        for (int i = 0; i < ETL; i++) {
            vA[i] = ta[i]; vB[i] = tb[i];
            na += ta[i] * ta[i]; nb += tb[i] * tb[i];
        }
        na = sqrtf(na); nb = sqrtf(nb);
        inv1A = (na > 0.0f) ? 1.0f / na : 0.0f;
        inv1B = (nb > 0.0f) ? 1.0f / nb : 0.0f;
    }

    float bestP0, bestP1;   // per-pixel final best score
    int idxP0 = 0, idxP1 = 0;

    if (M <= 8) {
        // ---- build packed signals ----
        int mm = (M < 8) ? M : 8;
        float wA[8], wB[8];
        float nA = 0.0f, nB = 0.0f;
#pragma unroll
        for (int j = 0; j < 8; j++) {
            float xa = (j < mm) ? vA[cols[j]] * inv1A : 0.0f;
            float xb = (j < mm) ? vB[cols[j]] * inv1B : 0.0f;
            wA[j] = xa; wB[j] = xb;
            nA += xa * xa; nB += xb * xb;
        }
        nA = sqrtf(nA); nB = sqrtf(nB);
        float i2A = (nA > 0.0f) ? 1.0f / nA : 0.0f;
        float i2B = (nB > 0.0f) ? 1.0f / nB : 0.0f;
#pragma unroll
        for (int j = 0; j < 8; j++) {
            float sa = wA[j] * i2A, sb = wB[j] * i2B;
            s2A += sa * sa; s2B += sb * sb;
            spkA[j] = pkf(sa, sa);
            spkB[j] = pkf(sb, sb);
        }

        // ---- main loop: 8 chunks x CH pairs, fmaxf-only best tracking ----
        float b00 = -INFINITY, b01 = -INFINITY;  // pixel0 even/odd slot
        float b10 = -INFINITY, b11 = -INFINITY;  // pixel1 even/odd slot
        int bc00 = 0, bc01 = 0, bc10 = 0, bc11 = 0;

#pragma unroll 1
        for (int c = 0; c < NCHUNK; c++) {
            float s00 = b00, s01 = b01, s10 = b10, s11 = b11;
            const int base = c * CH;
#pragma unroll 3
            for (int i = 0; i < CH; i++) {
                const int p = (base + i) * 4 + s;
                const float* rec = sm + p * 20;
                // inline both pixels sharing one record load
                uint4 qa = *(const uint4*)(rec);
                uint4 qb = *(const uint4*)(rec + 4);
                uint4 qc = *(const uint4*)(rec + 8);
                uint4 qd = *(const uint4*)(rec + 12);
                unsigned long long bias = *(const unsigned long long*)(rec + 16);
                unsigned long long u0 = pku(qa.x, qa.y), u1 = pku(qa.z, qa.w);
                unsigned long long u2 = pku(qb.x, qb.y), u3 = pku(qb.z, qb.w);
                unsigned long long u4 = pku(qc.x, qc.y), u5 = pku(qc.z, qc.w);
                unsigned long long u6 = pku(qd.x, qd.y), u7 = pku(qd.z, qd.w);
                unsigned long long accA = bias, accB = bias;
                fma2(accA, u0, spkA[0]); fma2(accB, u0, spkB[0]);
                fma2(accA, u1, spkA[1]); fma2(accB, u1, spkB[1]);
                fma2(accA, u2, spkA[2]); fma2(accB, u2, spkB[2]);
                fma2(accA, u3, spkA[3]); fma2(accB, u3, spkB[3]);
                fma2(accA, u4, spkA[4]); fma2(accB, u4, spkB[4]);
                fma2(accA, u5, spkA[5]); fma2(accB, u5, spkB[5]);
                fma2(accA, u6, spkA[6]); fma2(accB, u6, spkB[6]);
                fma2(accA, u7, spkA[7]); fma2(accB, u7, spkB[7]);
                float e0, o0, e1, o1;
                unpk(e0, o0, accA);
                unpk(e1, o1, accB);
                b00 = fmaxf(b00, e0); b01 = fmaxf(b01, o0);
                b10 = fmaxf(b10, e1); b11 = fmaxf(b11, o1);
            }
            if (b00 != s00) bc00 = c;
            if (b01 != s01) bc01 = c;
            if (b10 != s10) bc10 = c;
            if (b11 != s11) bc11 = c;
        }

        // ---- index recovery: rescan the single winning chunk per pixel ----
        bestP0 = fmaxf(b00, b01);
        bestP1 = fmaxf(b10, b11);
        {
            int ce = (b00 == bestP0) ? bc00 : INT_MAX;
            int co = (b01 == bestP0) ? bc01 : INT_MAX;
            int c = min(ce, co);
            int idx = INT_MAX;
            const int base = c * CH;
            for (int i = 0; i < CH; i++) {
                const int p = (base + i) * 4 + s;
                unsigned long long acc = score_pair(sm + p * 20, spkA);
                float se, so;
                unpk(se, so, acc);
                if (se == bestP0) idx = min(idx, 2 * p);
                if (so == bestP0) idx = min(idx, 2 * p + 1);
            }
            idxP0 = idx;
        }
        {
            int ce = (b10 == bestP1) ? bc10 : INT_MAX;
            int co = (b11 == bestP1) ? bc11 : INT_MAX;
            int c = min(ce, co);
            int idx = INT_MAX;
            const int base = c * CH;
            for (int i = 0; i < CH; i++) {
                const int p = (base + i) * 4 + s;
                unsigned long long acc = score_pair(sm + p * 20, spkB);
                float se, so;
                unpk(se, so, acc);
                if (se == bestP1) idx = min(idx, 2 * p);
                if (so == bestP1) idx = min(idx, 2 * p + 1);
            }
            idxP1 = idx;
        }
    } else {
        // ---- generic fallback (any mask width): split 0 does full scan ----
        bestP0 = -INFINITY; bestP1 = -INFINITY;
        if (s == 0) {
            float sA[ETL], sB[ETL];
            float nA = 0.0f, nB = 0.0f;
#pragma unroll
            for (int i = 0; i < ETL; i++) {
                float m = (delta[i] * 1e-3f < 1e-3f) ? 1.0f : 0.0f;
                float ua = vA[i] * inv1A * m;
                float ub = vB[i] * inv1B * m;
                sA[i] = ua; sB[i] = ub;
                nA += ua * ua; nB += ub * ub;
            }
            nA = sqrtf(nA); nB = sqrtf(nB);
            float i2A = (nA > 0.0f) ? 1.0f / nA : 0.0f;
            float i2B = (nB > 0.0f) ? 1.0f / nB : 0.0f;
#pragma unroll
            for (int i = 0; i < ETL; i++) {
                sA[i] *= i2A; sB[i] *= i2B;
                s2A += sA[i] * sA[i]; s2B += sB[i] * sB[i];
            }
            for (int d = 0; d < D; d++) {
                float da = 0.0f, dbd = 0.0f;
#pragma unroll
                for (int i = 0; i < ETL; i++) {
                    float f = g_full[d * ETL + i];
                    da += f * sA[i]; dbd += f * sB[i];
                }
                float ca = da - 0.5f * g_d2[d];
                float cb = dbd - 0.5f * g_d2[d];
                if (ca > bestP0) { bestP0 = ca; idxP0 = d; }
                if (cb > bestP1) { bestP1 = cb; idxP1 = d; }
            }
        }
    }

    // ---- merge the 4 splits (lanes g*4 .. g*4+3): max score, min index ----
#pragma unroll
    for (int off = 1; off <= 2; off <<= 1) {
        float ob0 = __shfl_xor_sync(0xffffffffu, bestP0, off);
        int oi0 = __shfl_xor_sync(0xffffffffu, idxP0, off);
        float ob1 = __shfl_xor_sync(0xffffffffu, bestP1, off);
        int oi1 = __shfl_xor_sync(0xffffffffu, idxP1, off);
        if (ob0 > bestP0 || (ob0 == bestP0 && oi0 < idxP0)) { bestP0 = ob0; idxP0 = oi0; }
        if (ob1 > bestP1 || (ob1 == bestP1 && oi1 < idxP1)) { bestP1 = ob1; idxP1 = oi1; }
    }

    if (s == 0) {
        if (idxP0 < 0 || idxP0 >= D) idxP0 = 0;  // safety (cannot trigger)
        if (idxP1 < 0 || idxP1 >= D) idxP1 = 0;
        if (v0) {
            float md = sqrtf(fmaxf(s2A - 2.0f * bestP0, 0.0f));
            out[pix0]         = t2s[idxP0];
            out[N + pix0]     = b1s[idxP0];
            out[2 * N + pix0] = md;
        }
        if (v1) {
            float md = sqrtf(fmaxf(s2B - 2.0f * bestP1, 0.0f));
            out[pix1]         = t2s[idxP1];
            out[N + pix1]     = b1s[idxP1];
            out[2 * N + pix1] = md;
        }
    }
}

// ---------------------------------------------------------------------------
extern "C" void kernel_launch(void* const* d_in, const int* in_sizes, int n_in,
                              void* d_out, int out_size) {
    const float* sig   = (const float*)d_in[0];
    const float* dbmag = (const float*)d_in[1];
    const float* t2s   = (const float*)d_in[2];
    const float* b1s   = (const float*)d_in[3];
    const float* delta = (const float*)d_in[4];

    const int D = in_sizes[2];                // 4000
    const int N = in_sizes[0] / ETL;          // 36864
    const int NP = (D + 1) / 2;               // 2000 pairs
    const int Q  = (NP + 3) / 4;              // pairs per split = 500
    const int CH = (Q + NCHUNK - 1) / NCHUNK; // 63
    const int NP2 = CH * NCHUNK * 4;          // 2016 padded pairs
    const size_t smem = (size_t)NP2 * 20 * sizeof(float);  // 161280 B

    cudaFuncSetAttribute(k_match, cudaFuncAttributeMaxDynamicSharedMemorySize,
                         (int)smem);

    k_atoms<<<(NP2 * 2 + 127) / 128, 128>>>(dbmag, delta, D, NP2);
    int blocks = (N + 255) / 256;
    k_match<<<blocks, 512, smem>>>(sig, t2s, b1s, delta, (float*)d_out,
                                   N, D, NP2, CH);
}

// round 10
// speedup vs baseline: 1.7489x; 1.4543x over previous
#include <cuda_runtime.h>
#include <math.h>
#include <limits.h>

// ---------------------------------------------------------------------------
// DictionaryMatchingTv — GB300 sm_103a
//   inputs: slice_signal [N*16] f32, db_mag [D*16] f32, db_t2s_s [D] f32,
//           db_b1s [D] f32, delta_t_r2p_ms [16] f32
//   output: [t2 (N) | b1 (N) | min_dist (N)] f32
//
// Atom PAIRS packed into f32x2 lanes. Each thread matches 4 pixels against an
// 8-way interleaved slice of the pair list (p ≡ s mod 8), so each 80-B record
// load (18 smem crossbar phases) feeds 32 fma2 — fma and LDS co-binding.
// Best tracked index-free via fmaxf + per-chunk snapshots; argmax recovered by
// exact-equality rescan of the winning chunk (identical asm chain -> bitwise
// reproducible scores).
// ---------------------------------------------------------------------------

#define ETL     16
#define MAXD    8192
#define NCHUNK  8
#define NSPLIT  8
#define NPIX    4
#define MAXNP2  4096

__device__ float g_recs[MAXNP2 * 20];   // 80-B records: 16 vals + 2 bias + pad
__device__ float g_full[MAXD * ETL];    // normalized atoms (generic fallback)
__device__ float g_d2[MAXD];            // ||atom||^2     (generic fallback)

// ---- f32x2 packed helpers (Blackwell-only PTX) -----------------------------
__device__ __forceinline__ unsigned long long pkf(float lo, float hi) {
    unsigned long long r;
    asm("mov.b64 %0, {%1, %2};" : "=l"(r) : "f"(lo), "f"(hi));
    return r;
}
__device__ __forceinline__ unsigned long long pku(unsigned lo, unsigned hi) {
    unsigned long long r;
    asm("mov.b64 %0, {%1, %2};" : "=l"(r) : "r"(lo), "r"(hi));
    return r;
}
__device__ __forceinline__ void unpk(float& lo, float& hi, unsigned long long v) {
    asm("mov.b64 {%0, %1}, %2;" : "=f"(lo), "=f"(hi) : "l"(v));
}
__device__ __forceinline__ void fma2(unsigned long long& d, unsigned long long a,
                                     unsigned long long b) {
    asm("fma.rn.f32x2 %0, %1, %2, %0;" : "+l"(d) : "l"(a), "l"(b));
}

// Single scoring definition shared by main loop & rescan => bitwise identical.
__device__ __forceinline__ unsigned long long score_pair(
    const float* __restrict__ rec, const unsigned long long* __restrict__ spk) {
    uint4 qa = *(const uint4*)(rec);
    uint4 qb = *(const uint4*)(rec + 4);
    uint4 qc = *(const uint4*)(rec + 8);
    uint4 qd = *(const uint4*)(rec + 12);
    unsigned long long acc = *(const unsigned long long*)(rec + 16);
    fma2(acc, pku(qa.x, qa.y), spk[0]);
    fma2(acc, pku(qa.z, qa.w), spk[1]);
    fma2(acc, pku(qb.x, qb.y), spk[2]);
    fma2(acc, pku(qb.z, qb.w), spk[3]);
    fma2(acc, pku(qc.x, qc.y), spk[4]);
    fma2(acc, pku(qc.z, qc.w), spk[5]);
    fma2(acc, pku(qd.x, qd.y), spk[6]);
    fma2(acc, pku(qd.z, qd.w), spk[7]);
    return acc;
}

// ---------------------------------------------------------------------------
// Kernel 1: normalize atoms, build 80-B pair records (pad pairs get -1e30 bias)
// ---------------------------------------------------------------------------
__global__ void k_atoms(const float* __restrict__ db_mag,
                        const float* __restrict__ delta, int D, int NP2) {
    int a = blockIdx.x * blockDim.x + threadIdx.x;
    if (a >= NP2 * 2) return;

    int cols[ETL];
    int M = 0;
#pragma unroll
    for (int e = 0; e < ETL; e++) {
        if (delta[e] * 1e-3f < 1e-3f) cols[M++] = e;
    }

    int pr = a >> 1, slot = a & 1;
    float c[8];
#pragma unroll
    for (int j = 0; j < 8; j++) c[j] = 0.0f;
    float bias = -1e30f;

    if (a < D) {
        float w[ETL];
        float nn = 0.0f;
#pragma unroll
        for (int i = 0; i < ETL; i++) {
            float m = (delta[i] * 1e-3f < 1e-3f) ? 1.0f : 0.0f;
            float v = db_mag[a * ETL + i] * m;
            w[i] = v;
            nn += v * v;
        }
        nn = sqrtf(nn);
        float inv = (nn > 0.0f) ? 1.0f / nn : 0.0f;  // nan_to_num semantics
        float db[ETL];
        float d2 = 0.0f;
#pragma unroll
        for (int i = 0; i < ETL; i++) {
            db[i] = w[i] * inv;
            d2 += db[i] * db[i];
            g_full[a * ETL + i] = db[i];
        }
        g_d2[a] = d2;
        bias = -0.5f * d2;
        int mm = (M < 8) ? M : 8;
        for (int j = 0; j < mm; j++) c[j] = db[cols[j]];
    }

    float* rec = &g_recs[pr * 20];
#pragma unroll
    for (int j = 0; j < 8; j++) rec[j * 2 + slot] = c[j];
    rec[16 + slot] = bias;
    if (slot == 0) { rec[18] = 0.0f; rec[19] = 0.0f; }
}

// ---------------------------------------------------------------------------
// Kernel 2: match. 512 thr/block, 256 px/block, 4 px/thread, 8-way split.
// ---------------------------------------------------------------------------
__global__ void __launch_bounds__(512, 1)
k_match(const float* __restrict__ sig, const float* __restrict__ t2s,
        const float* __restrict__ b1s, const float* __restrict__ delta,
        float* __restrict__ out, int N, int D, int NP2, int CH) {
    extern __shared__ float sm[];

    // ---- stage records to shared ----
    {
        const uint4* src = (const uint4*)g_recs;
        uint4* dst = (uint4*)sm;
        const int n4 = NP2 * 5;
        for (int i = threadIdx.x; i < n4; i += blockDim.x) dst[i] = src[i];
    }

    int cols[ETL];
    int M = 0;
#pragma unroll
    for (int e = 0; e < ETL; e++) {
        if (delta[e] * 1e-3f < 1e-3f) cols[M++] = e;
    }
    __syncthreads();

    const int tid = threadIdx.x;
    const int s = tid & (NSPLIT - 1);           // dictionary split 0..7
    const int g = tid >> 3;                     // pixel group 0..63
    const int pixBase = blockIdx.x * 256 + g * NPIX;

    // ---- per-pixel two-step normalize -> packed signals ----
    unsigned long long spk[NPIX][8];
    float s2[NPIX];
    const bool fast = (M <= 8);
    {
        int mm = (M < 8) ? M : 8;
#pragma unroll
        for (int k = 0; k < NPIX; k++) {
            int pix = pixBase + k;
            int n = (pix < N) ? pix : (N - 1);
            const float4* sp = (const float4*)(sig + (size_t)n * ETL);
            float4 f0 = sp[0], f1 = sp[1], f2 = sp[2], f3 = sp[3];
            float v[ETL] = {f0.x, f0.y, f0.z, f0.w, f1.x, f1.y, f1.z, f1.w,
                            f2.x, f2.y, f2.z, f2.w, f3.x, f3.y, f3.z, f3.w};
            float n1 = 0.0f;
#pragma unroll
            for (int i = 0; i < ETL; i++) n1 += v[i] * v[i];
            n1 = sqrtf(n1);
            float inv1 = (n1 > 0.0f) ? 1.0f / n1 : 0.0f;
            float w[8];
            float n2 = 0.0f;
#pragma unroll
            for (int j = 0; j < 8; j++) {
                float x = (fast && j < mm) ? v[cols[j]] * inv1 : 0.0f;
                w[j] = x;
                n2 += x * x;
            }
            n2 = sqrtf(n2);
            float inv2 = (n2 > 0.0f) ? 1.0f / n2 : 0.0f;
            float acc = 0.0f;
#pragma unroll
            for (int j = 0; j < 8; j++) {
                float sv = w[j] * inv2;
                acc += sv * sv;
                spk[k][j] = pkf(sv, sv);
            }
            s2[k] = acc;
        }
    }

    float best[NPIX];
    int idx[NPIX];
#pragma unroll
    for (int k = 0; k < NPIX; k++) { best[k] = -INFINITY; idx[k] = INT_MAX; }

    if (fast) {
        int bc[NPIX];
#pragma unroll
        for (int k = 0; k < NPIX; k++) bc[k] = 0;

#pragma unroll 1
        for (int c = 0; c < NCHUNK; c++) {
            float snap0 = best[0], snap1 = best[1], snap2 = best[2], snap3 = best[3];
            const int base = c * CH;
#pragma unroll 2
            for (int i = 0; i < CH; i++) {
                const int p = (base + i) * NSPLIT + s;
                const float* rec = sm + p * 20;
                uint4 qa = *(const uint4*)(rec);
                uint4 qb = *(const uint4*)(rec + 4);
                uint4 qc = *(const uint4*)(rec + 8);
                uint4 qd = *(const uint4*)(rec + 12);
                unsigned long long bias = *(const unsigned long long*)(rec + 16);
                unsigned long long u0 = pku(qa.x, qa.y), u1 = pku(qa.z, qa.w);
                unsigned long long u2 = pku(qb.x, qb.y), u3 = pku(qb.z, qb.w);
                unsigned long long u4 = pku(qc.x, qc.y), u5 = pku(qc.z, qc.w);
                unsigned long long u6 = pku(qd.x, qd.y), u7 = pku(qd.z, qd.w);
                unsigned long long a0 = bias, a1 = bias, a2 = bias, a3 = bias;
                fma2(a0, u0, spk[0][0]); fma2(a1, u0, spk[1][0]);
                fma2(a2, u0, spk[2][0]); fma2(a3, u0, spk[3][0]);
                fma2(a0, u1, spk[0][1]); fma2(a1, u1, spk[1][1]);
                fma2(a2, u1, spk[2][1]); fma2(a3, u1, spk[3][1]);
                fma2(a0, u2, spk[0][2]); fma2(a1, u2, spk[1][2]);
                fma2(a2, u2, spk[2][2]); fma2(a3, u2, spk[3][2]);
                fma2(a0, u3, spk[0][3]); fma2(a1, u3, spk[1][3]);
                fma2(a2, u3, spk[2][3]); fma2(a3, u3, spk[3][3]);
                fma2(a0, u4, spk[0][4]); fma2(a1, u4, spk[1][4]);
                fma2(a2, u4, spk[2][4]); fma2(a3, u4, spk[3][4]);
                fma2(a0, u5, spk[0][5]); fma2(a1, u5, spk[1][5]);
                fma2(a2, u5, spk[2][5]); fma2(a3, u5, spk[3][5]);
                fma2(a0, u6, spk[0][6]); fma2(a1, u6, spk[1][6]);
                fma2(a2, u6, spk[2][6]); fma2(a3, u6, spk[3][6]);
                fma2(a0, u7, spk[0][7]); fma2(a1, u7, spk[1][7]);
                fma2(a2, u7, spk[2][7]); fma2(a3, u7, spk[3][7]);
                float e, o;
                unpk(e, o, a0); best[0] = fmaxf(best[0], fmaxf(e, o));
                unpk(e, o, a1); best[1] = fmaxf(best[1], fmaxf(e, o));
                unpk(e, o, a2); best[2] = fmaxf(best[2], fmaxf(e, o));
                unpk(e, o, a3); best[3] = fmaxf(best[3], fmaxf(e, o));
            }
            if (best[0] != snap0) bc[0] = c;
            if (best[1] != snap1) bc[1] = c;
            if (best[2] != snap2) bc[2] = c;
            if (best[3] != snap3) bc[3] = c;
        }

        // ---- index recovery: exact-equality rescan of the winning chunk ----
#pragma unroll 1
        for (int k = 0; k < NPIX; k++) {
            int id = INT_MAX;
            const int base = bc[k] * CH;
            for (int i = 0; i < CH; i++) {
                const int p = (base + i) * NSPLIT + s;
                unsigned long long acc = score_pair(sm + p * 20, spk[k]);
                float e, o;
                unpk(e, o, acc);
                if (e == best[k]) id = min(id, 2 * p);
                if (o == best[k]) id = min(id, 2 * p + 1);
            }
            idx[k] = id;
        }
    } else {
        // ---- generic fallback (any mask width): split 0 does full scan ----
        if (s == 0) {
#pragma unroll 1
            for (int k = 0; k < NPIX; k++) {
                int pix = pixBase + k;
                int n = (pix < N) ? pix : (N - 1);
                float sv[ETL];
                float n1 = 0.0f;
#pragma unroll
                for (int i = 0; i < ETL; i++) {
                    float x = sig[(size_t)n * ETL + i];
                    sv[i] = x;
                    n1 += x * x;
                }
                n1 = sqrtf(n1);
                float inv1 = (n1 > 0.0f) ? 1.0f / n1 : 0.0f;
                float n2 = 0.0f;
#pragma unroll
                for (int i = 0; i < ETL; i++) {
                    float m = (delta[i] * 1e-3f < 1e-3f) ? 1.0f : 0.0f;
                    sv[i] = sv[i] * inv1 * m;
                    n2 += sv[i] * sv[i];
                }
                n2 = sqrtf(n2);
                float inv2 = (n2 > 0.0f) ? 1.0f / n2 : 0.0f;
                float ss = 0.0f;
#pragma unroll
                for (int i = 0; i < ETL; i++) { sv[i] *= inv2; ss += sv[i] * sv[i]; }
                s2[k] = ss;
                float b = -INFINITY;
                int bi = 0;
                for (int d = 0; d < D; d++) {
                    float dot = 0.0f;
#pragma unroll
                    for (int i = 0; i < ETL; i++) dot += g_full[d * ETL + i] * sv[i];
                    float sc = dot - 0.5f * g_d2[d];
                    if (sc > b) { b = sc; bi = d; }
                }
                best[k] = b;
                idx[k] = bi;
            }
        }
    }

    // ---- merge the 8 splits (8 consecutive lanes): max score, min index ----
#pragma unroll
    for (int off = 1; off <= 4; off <<= 1) {
#pragma unroll
        for (int k = 0; k < NPIX; k++) {
            float ob = __shfl_xor_sync(0xffffffffu, best[k], off);
            int oi = __shfl_xor_sync(0xffffffffu, idx[k], off);
            if (ob > best[k] || (ob == best[k] && oi < idx[k])) {
                best[k] = ob;
                idx[k] = oi;
            }
        }
    }

    if (s == 0) {
#pragma unroll
        for (int k = 0; k < NPIX; k++) {
            int pix = pixBase + k;
            if (pix < N) {
                int a = idx[k];
                if (a < 0 || a >= D) a = 0;  // safety (cannot trigger)
                float md = sqrtf(fmaxf(s2[k] - 2.0f * best[k], 0.0f));
                out[pix]         = t2s[a];
                out[N + pix]     = b1s[a];
                out[2 * N + pix] = md;
            }
        }
    }
}

// ---------------------------------------------------------------------------
extern "C" void kernel_launch(void* const* d_in, const int* in_sizes, int n_in,
                              void* d_out, int out_size) {
    const float* sig   = (const float*)d_in[0];
    const float* dbmag = (const float*)d_in[1];
    const float* t2s   = (const float*)d_in[2];
    const float* b1s   = (const float*)d_in[3];
    const float* delta = (const float*)d_in[4];

    const int D = in_sizes[2];                    // 4000
    const int N = in_sizes[0] / ETL;              // 36864
    const int NP = (D + 1) / 2;                   // 2000 pairs
    const int Q  = (NP + NSPLIT - 1) / NSPLIT;    // 250 pairs per split
    const int CH = (Q + NCHUNK - 1) / NCHUNK;     // 32
    const int NP2 = CH * NCHUNK * NSPLIT;         // 2048 padded pairs
    const size_t smem = (size_t)NP2 * 20 * sizeof(float);  // 163840 B

    cudaFuncSetAttribute(k_match, cudaFuncAttributeMaxDynamicSharedMemorySize,
                         (int)smem);

    k_atoms<<<(NP2 * 2 + 127) / 128, 128>>>(dbmag, delta, D, NP2);
    int blocks = (N + 255) / 256;
    k_match<<<blocks, 512, smem>>>(sig, t2s, b1s, delta, (float*)d_out,
                                   N, D, NP2, CH);
}

// round 13
// speedup vs baseline: 1.9425x; 1.1107x over previous
#include <cuda_runtime.h>
#include <math.h>
#include <limits.h>

// ---------------------------------------------------------------------------
// DictionaryMatchingTv — GB300 sm_103a
//   inputs: slice_signal [N*16] f32, db_mag [D*16] f32, db_t2s_s [D] f32,
//           db_b1s [D] f32, delta_t_r2p_ms [16] f32
//   output: [t2 (N) | b1 (N) | min_dist (N)] f32
//
// v13: 256 thr/block (1 block/SM), 8 pixels/thread, 8-way dictionary split.
// Atom pairs in f32x2 lane0/lane1; signals packed per pixel-pair in BOTH
// orders (spp / swapped sps) so each 80-B record feeds 16 atom-pixel scores
// with 64 fma2 and no per-record packing movs. Best tracked with fmaxf
// (FMNMX = ALU pipe) + per-chunk snapshots; index recovered by rescanning the
// winning chunk with the IDENTICAL packed fma2 chains (bitwise reproducible,
// proven in rounds 7-10). Cold fallback full-rescan guards the impossible.
// score = dot - 0.5*d2 (argmax score == argmin dist); dist^2 = s2 - 2*score.
// ---------------------------------------------------------------------------

#define ETL     16
#define NSPLIT  8
#define NPIX    8
#define CHN     8      // records per chunk (per thread)
#define MAXNP2  4096

__device__ float g_recs[MAXNP2 * 20];   // 80-B records: 16 vals + 2 bias + pad
__device__ float g_full[8192 * ETL];    // normalized atoms (generic fallback)
__device__ float g_d2[8192];            // ||atom||^2     (generic fallback)

// ---- f32x2 packed helpers (Blackwell-only PTX) -----------------------------
__device__ __forceinline__ unsigned long long pkf(float lo, float hi) {
    unsigned long long r;
    asm("mov.b64 %0, {%1, %2};" : "=l"(r) : "f"(lo), "f"(hi));
    return r;
}
__device__ __forceinline__ unsigned long long pku(unsigned lo, unsigned hi) {
    unsigned long long r;
    asm("mov.b64 %0, {%1, %2};" : "=l"(r) : "r"(lo), "r"(hi));
    return r;
}
__device__ __forceinline__ void unpk(float& lo, float& hi, unsigned long long v) {
    asm("mov.b64 {%0, %1}, %2;" : "=f"(lo), "=f"(hi) : "l"(v));
}
__device__ __forceinline__ void fma2(unsigned long long& d, unsigned long long a,
                                     unsigned long long b) {
    asm("fma.rn.f32x2 %0, %1, %2, %0;" : "+l"(d) : "l"(a), "l"(b));
}

// ---------------------------------------------------------------------------
// Kernel 1: normalize atoms, build 80-B pair records.
//   rec[2j+slot] = compacted SE value j of atom 2*pr+slot
//   rec[16+slot] = -0.5*d2   (pad atoms: -1e30, can never win)
// ---------------------------------------------------------------------------
__global__ void k_atoms(const float* __restrict__ db_mag,
                        const float* __restrict__ delta, int D, int NP2) {
    int a = blockIdx.x * blockDim.x + threadIdx.x;
    if (a >= NP2 * 2) return;

    int cols[ETL];
    int M = 0;
#pragma unroll
    for (int e = 0; e < ETL; e++) {
        if (delta[e] * 1e-3f < 1e-3f) cols[M++] = e;
    }

    int pr = a >> 1, slot = a & 1;
    float c[8];
#pragma unroll
    for (int j = 0; j < 8; j++) c[j] = 0.0f;
    float bias = -1e30f;  // pad sentinel

    if (a < D) {
        float w[ETL];
        float nn = 0.0f;
#pragma unroll
        for (int i = 0; i < ETL; i++) {
            float m = (delta[i] * 1e-3f < 1e-3f) ? 1.0f : 0.0f;
            float v = db_mag[a * ETL + i] * m;
            w[i] = v;
            nn += v * v;
        }
        nn = sqrtf(nn);
        float inv = (nn > 0.0f) ? 1.0f / nn : 0.0f;  // nan_to_num semantics
        float db[ETL];
        float d2 = 0.0f;
#pragma unroll
        for (int i = 0; i < ETL; i++) {
            db[i] = w[i] * inv;
            d2 += db[i] * db[i];
            g_full[a * ETL + i] = db[i];
        }
        g_d2[a] = d2;
        bias = -0.5f * d2;
        int mm = (M < 8) ? M : 8;
        for (int j = 0; j < mm; j++) c[j] = db[cols[j]];
    }

    float* rec = &g_recs[pr * 20];
#pragma unroll
    for (int j = 0; j < 8; j++) rec[j * 2 + slot] = c[j];
    rec[16 + slot] = bias;
    if (slot == 0) { rec[18] = 0.0f; rec[19] = 0.0f; }
}

// ---------------------------------------------------------------------------
// Kernel 2: match. 256 thr/block, 256 px/block, 8 px/thread, 8-way split.
// ---------------------------------------------------------------------------
__global__ void __launch_bounds__(256, 1)
k_match(const float* __restrict__ sig, const float* __restrict__ t2s,
        const float* __restrict__ b1s, const float* __restrict__ delta,
        float* __restrict__ out, int N, int D, int NP2, int nchunks) {
    extern __shared__ float sm[];

    // ---- stage records to shared ----
    {
        const uint4* src = (const uint4*)g_recs;
        uint4* dst = (uint4*)sm;
        const int n4 = NP2 * 5;
        for (int i = threadIdx.x; i < n4; i += blockDim.x) dst[i] = src[i];
    }

    int cols[ETL];
    int M = 0;
#pragma unroll
    for (int e = 0; e < ETL; e++) {
        if (delta[e] * 1e-3f < 1e-3f) cols[M++] = e;
    }
    __syncthreads();

    const int tid = threadIdx.x;
    const int s = tid & (NSPLIT - 1);
    const int g = tid >> 3;
    const int pixBase = blockIdx.x * 256 + g * NPIX;
    const bool fast = (M <= 8);

    // ---- per-pixel two-step normalize -> packed pixel-pair signals ----
    unsigned long long spp[4][8];  // (s_{2pp,j}, s_{2pp+1,j})
    unsigned long long sps[4][8];  // swapped order
    float s2[NPIX];
    {
        int mm = (M < 8) ? M : 8;
        float sv[NPIX][8];
#pragma unroll
        for (int k = 0; k < NPIX; k++) {
            int pix = pixBase + k;
            int n = (pix < N) ? pix : (N - 1);
            const float4* sp = (const float4*)(sig + (size_t)n * ETL);
            float4 f0 = sp[0], f1 = sp[1], f2 = sp[2], f3 = sp[3];
            float v[ETL] = {f0.x, f0.y, f0.z, f0.w, f1.x, f1.y, f1.z, f1.w,
                            f2.x, f2.y, f2.z, f2.w, f3.x, f3.y, f3.z, f3.w};
            float n1 = 0.0f;
#pragma unroll
            for (int i = 0; i < ETL; i++) n1 += v[i] * v[i];
            n1 = sqrtf(n1);
            float inv1 = (n1 > 0.0f) ? 1.0f / n1 : 0.0f;
            float w[8];
            float n2 = 0.0f;
#pragma unroll
            for (int j = 0; j < 8; j++) {
                float x = (fast && j < mm) ? v[cols[j]] * inv1 : 0.0f;
                w[j] = x;
                n2 += x * x;
            }
            n2 = sqrtf(n2);
            float inv2 = (n2 > 0.0f) ? 1.0f / n2 : 0.0f;
            float acc = 0.0f;
#pragma unroll
            for (int j = 0; j < 8; j++) {
                float q = w[j] * inv2;
                acc += q * q;
                sv[k][j] = q;
            }
            s2[k] = acc;
        }
#pragma unroll
        for (int pp = 0; pp < 4; pp++) {
#pragma unroll
            for (int j = 0; j < 8; j++) {
                spp[pp][j] = pkf(sv[2 * pp][j], sv[2 * pp + 1][j]);
                sps[pp][j] = pkf(sv[2 * pp + 1][j], sv[2 * pp][j]);
            }
        }
    }

    float best[NPIX];
    int idx[NPIX];
    int bc[NPIX];
#pragma unroll
    for (int k = 0; k < NPIX; k++) {
        best[k] = -INFINITY; idx[k] = INT_MAX; bc[k] = 0;
    }

    if (fast) {
#pragma unroll 1
        for (int c = 0; c < nchunks; c++) {
            float snap[NPIX];
#pragma unroll
            for (int k = 0; k < NPIX; k++) snap[k] = best[k];
            const int base = c * CHN;
#pragma unroll 2
            for (int i = 0; i < CHN; i++) {
                const int p = (base + i) * NSPLIT + s;
                const float* rec = sm + p * 20;
                uint4 qa = *(const uint4*)(rec);
                uint4 qb = *(const uint4*)(rec + 4);
                uint4 qc = *(const uint4*)(rec + 8);
                uint4 qd = *(const uint4*)(rec + 12);
                unsigned long long bias = *(const unsigned long long*)(rec + 16);
                unsigned long long u0 = pku(qa.x, qa.y), u1 = pku(qa.z, qa.w);
                unsigned long long u2 = pku(qb.x, qb.y), u3 = pku(qb.z, qb.w);
                unsigned long long u4 = pku(qc.x, qc.y), u5 = pku(qc.z, qc.w);
                unsigned long long u6 = pku(qd.x, qd.y), u7 = pku(qd.z, qd.w);
#pragma unroll
                for (int pp = 0; pp < 4; pp++) {
                    unsigned long long aA = bias, aB = bias;
                    fma2(aA, u0, spp[pp][0]); fma2(aB, u0, sps[pp][0]);
                    fma2(aA, u1, spp[pp][1]); fma2(aB, u1, sps[pp][1]);
                    fma2(aA, u2, spp[pp][2]); fma2(aB, u2, sps[pp][2]);
                    fma2(aA, u3, spp[pp][3]); fma2(aB, u3, sps[pp][3]);
                    fma2(aA, u4, spp[pp][4]); fma2(aB, u4, sps[pp][4]);
                    fma2(aA, u5, spp[pp][5]); fma2(aB, u5, sps[pp][5]);
                    fma2(aA, u6, spp[pp][6]); fma2(aB, u6, sps[pp][6]);
                    fma2(aA, u7, spp[pp][7]); fma2(aB, u7, sps[pp][7]);
                    float lo, hi;
                    // aA = (E·px_even, O·px_odd)
                    unpk(lo, hi, aA);
                    best[2 * pp]     = fmaxf(best[2 * pp],     lo);
                    best[2 * pp + 1] = fmaxf(best[2 * pp + 1], hi);
                    // aB = (E·px_odd, O·px_even)
                    unpk(lo, hi, aB);
                    best[2 * pp + 1] = fmaxf(best[2 * pp + 1], lo);
                    best[2 * pp]     = fmaxf(best[2 * pp],     hi);
                }
            }
#pragma unroll
            for (int k = 0; k < NPIX; k++)
                if (best[k] != snap[k]) bc[k] = c;
        }

        // ---- index recovery: rescan winning chunk with IDENTICAL chains ----
#pragma unroll
        for (int k = 0; k < NPIX; k++) {
            const float tgt = best[k];
            const int pp = k >> 1;
            const int odd = k & 1;
            int id = INT_MAX;
            const int base = bc[k] * CHN;
#pragma unroll 1
            for (int i = 0; i < CHN; i++) {
                const int p = (base + i) * NSPLIT + s;
                const float* rec = sm + p * 20;
                uint4 qa = *(const uint4*)(rec);
                uint4 qb = *(const uint4*)(rec + 4);
                uint4 qc = *(const uint4*)(rec + 8);
                uint4 qd = *(const uint4*)(rec + 12);
                unsigned long long bias = *(const unsigned long long*)(rec + 16);
                unsigned long long u0 = pku(qa.x, qa.y), u1 = pku(qa.z, qa.w);
                unsigned long long u2 = pku(qb.x, qb.y), u3 = pku(qb.z, qb.w);
                unsigned long long u4 = pku(qc.x, qc.y), u5 = pku(qc.z, qc.w);
                unsigned long long u6 = pku(qd.x, qd.y), u7 = pku(qd.z, qd.w);
                unsigned long long aA = bias, aB = bias;
                fma2(aA, u0, spp[pp][0]); fma2(aB, u0, sps[pp][0]);
                fma2(aA, u1, spp[pp][1]); fma2(aB, u1, sps[pp][1]);
                fma2(aA, u2, spp[pp][2]); fma2(aB, u2, sps[pp][2]);
                fma2(aA, u3, spp[pp][3]); fma2(aB, u3, sps[pp][3]);
                fma2(aA, u4, spp[pp][4]); fma2(aB, u4, sps[pp][4]);
                fma2(aA, u5, spp[pp][5]); fma2(aB, u5, sps[pp][5]);
                fma2(aA, u6, spp[pp][6]); fma2(aB, u6, sps[pp][6]);
                fma2(aA, u7, spp[pp][7]); fma2(aB, u7, sps[pp][7]);
                float loA, hiA, loB, hiB;
                unpk(loA, hiA, aA);
                unpk(loB, hiB, aB);
                // pixel k even: even-atom score = aA.lo, odd-atom = aB.hi
                // pixel k odd : even-atom score = aB.lo, odd-atom = aA.hi
                float se = odd ? loB : loA;
                float so = odd ? hiA : hiB;
                if (se == tgt) id = min(id, 2 * p);
                if (so == tgt) id = min(id, 2 * p + 1);
            }
            // cold safety net: full same-chain rescan with its own argmax
            if (id == INT_MAX) {
                float cb = -INFINITY;
#pragma unroll 1
                for (int p = s; p < NP2; p += NSPLIT) {
                    const float* rec = sm + p * 20;
                    uint4 qa = *(const uint4*)(rec);
                    uint4 qb = *(const uint4*)(rec + 4);
                    uint4 qc = *(const uint4*)(rec + 8);
                    uint4 qd = *(const uint4*)(rec + 12);
                    unsigned long long bias = *(const unsigned long long*)(rec + 16);
                    unsigned long long u0 = pku(qa.x, qa.y), u1 = pku(qa.z, qa.w);
                    unsigned long long u2 = pku(qb.x, qb.y), u3 = pku(qb.z, qb.w);
                    unsigned long long u4 = pku(qc.x, qc.y), u5 = pku(qc.z, qc.w);
                    unsigned long long u6 = pku(qd.x, qd.y), u7 = pku(qd.z, qd.w);
                    unsigned long long aA = bias, aB = bias;
                    fma2(aA, u0, spp[pp][0]); fma2(aB, u0, sps[pp][0]);
                    fma2(aA, u1, spp[pp][1]); fma2(aB, u1, sps[pp][1]);
                    fma2(aA, u2, spp[pp][2]); fma2(aB, u2, sps[pp][2]);
                    fma2(aA, u3, spp[pp][3]); fma2(aB, u3, sps[pp][3]);
                    fma2(aA, u4, spp[pp][4]); fma2(aB, u4, sps[pp][4]);
                    fma2(aA, u5, spp[pp][5]); fma2(aB, u5, sps[pp][5]);
                    fma2(aA, u6, spp[pp][6]); fma2(aB, u6, sps[pp][6]);
                    fma2(aA, u7, spp[pp][7]); fma2(aB, u7, sps[pp][7]);
                    float loA, hiA, loB, hiB;
                    unpk(loA, hiA, aA);
                    unpk(loB, hiB, aB);
                    float se = odd ? loB : loA;
                    float so = odd ? hiA : hiB;
                    if (se > cb) { cb = se; id = 2 * p; }
                    if (so > cb) { cb = so; id = 2 * p + 1; }
                }
                best[k] = cb;
            }
            idx[k] = id;
        }
    } else {
        // ---- generic fallback (any mask width): split 0 does full scan ----
        if (s == 0) {
#pragma unroll 1
            for (int k = 0; k < NPIX; k++) {
                int pix = pixBase + k;
                int n = (pix < N) ? pix : (N - 1);
                float sv[ETL];
                float n1 = 0.0f;
#pragma unroll
                for (int i = 0; i < ETL; i++) {
                    float x = sig[(size_t)n * ETL + i];
                    sv[i] = x;
                    n1 += x * x;
                }
                n1 = sqrtf(n1);
                float inv1 = (n1 > 0.0f) ? 1.0f / n1 : 0.0f;
                float n2 = 0.0f;
#pragma unroll
                for (int i = 0; i < ETL; i++) {
                    float m = (delta[i] * 1e-3f < 1e-3f) ? 1.0f : 0.0f;
                    sv[i] = sv[i] * inv1 * m;
                    n2 += sv[i] * sv[i];
                }
                n2 = sqrtf(n2);
                float inv2 = (n2 > 0.0f) ? 1.0f / n2 : 0.0f;
                float ss = 0.0f;
#pragma unroll
                for (int i = 0; i < ETL; i++) { sv[i] *= inv2; ss += sv[i] * sv[i]; }
                s2[k] = ss;
                float b = -INFINITY;
                int bi = 0;
                for (int d = 0; d < D; d++) {
                    float dot = 0.0f;
#pragma unroll
                    for (int i = 0; i < ETL; i++) dot += g_full[d * ETL + i] * sv[i];
                    float sc = dot - 0.5f * g_d2[d];
                    if (sc > b) { b = sc; bi = d; }
                }
                best[k] = b;
                idx[k] = bi;
            }
        }
    }

    // ---- merge the 8 splits: max score, min index on ties ----
#pragma unroll
    for (int off = 1; off <= 4; off <<= 1) {
#pragma unroll
        for (int k = 0; k < NPIX; k++) {
            float ob = __shfl_xor_sync(0xffffffffu, best[k], off);
            int oi = __shfl_xor_sync(0xffffffffu, idx[k], off);
            if (ob > best[k] || (ob == best[k] && oi < idx[k])) {
                best[k] = ob;
                idx[k] = oi;
            }
        }
    }

    if (s == 0) {
#pragma unroll
        for (int k = 0; k < NPIX; k++) {
            int pix = pixBase + k;
            if (pix < N) {
                int a = idx[k];
                if (a < 0 || a >= D) a = 0;  // safety (cannot trigger)
                float md = sqrtf(fmaxf(s2[k] - 2.0f * best[k], 0.0f));
                out[pix]         = t2s[a];
                out[N + pix]     = b1s[a];
                out[2 * N + pix] = md;
            }
        }
    }
}

// ---------------------------------------------------------------------------
extern "C" void kernel_launch(void* const* d_in, const int* in_sizes, int n_in,
                              void* d_out, int out_size) {
    const float* sig   = (const float*)d_in[0];
    const float* dbmag = (const float*)d_in[1];
    const float* t2s   = (const float*)d_in[2];
    const float* b1s   = (const float*)d_in[3];
    const float* delta = (const float*)d_in[4];

    const int D = in_sizes[2];                       // 4000
    const int N = in_sizes[0] / ETL;                 // 36864
    const int NP = (D + 1) / 2;                      // 2000 pairs
    const int Q  = (NP + NSPLIT - 1) / NSPLIT;       // 250 pairs/split
    const int nchunks = (Q + CHN - 1) / CHN;         // 32
    const int NP2 = nchunks * CHN * NSPLIT;          // 2048 padded pairs
    const size_t smem = (size_t)NP2 * 20 * sizeof(float);  // 163840 B

    cudaFuncSetAttribute(k_match, cudaFuncAttributeMaxDynamicSharedMemorySize,
                         (int)smem);

    k_atoms<<<(NP2 * 2 + 127) / 128, 128>>>(dbmag, delta, D, NP2);
    int blocks = (N + 255) / 256;
    k_match<<<blocks, 256, smem>>>(sig, t2s, b1s, delta, (float*)d_out,
                                   N, D, NP2, nchunks);
}